// round 4
// baseline (speedup 1.0000x reference)
#include <cuda_runtime.h>

// ---------------------------------------------------------------------------
// Average_Model_fwRF: out[b] = bias + sum_f feats[b,f] * W[f]
// Collapses to out[b] = bias + sum over all fmap/fc elements of
//   input[b, e] * coef[e], with coef batch-independent (347,240 floats).
// One cheap setup kernel builds coef; one streaming pass (~711 MB) reduces.
// ---------------------------------------------------------------------------

#define NB       512
#define NUNITS   18
#define COEF_TOT 347240

// per-layer element counts (C*H*H for conv, C for fc)
__constant__ int c_elems[8]    = {46656, 139968, 64896, 43264, 43264, 4096, 4096, 1000};
// coef buffer offsets (prefix sums of c_elems)
__constant__ int c_coef_off[9] = {0, 46656, 186624, 251520, 294784, 338048, 342144, 346240, 347240};
// W offsets: conv channels 64,192,384,256,256 then 1024,1024,1000
__constant__ int c_woff[8]     = {0, 64, 256, 640, 896, 1152, 2176, 3200};
// pixels per conv layer
__constant__ int c_P[5]        = {729, 729, 169, 169, 169};
// work decomposition: 18 units per batch
__constant__ int c_unit_layer[NUNITS] = {0,0, 1,1,1,1,1,1, 2,2,2, 3,3, 4,4, 5, 6, 7};
__constant__ int c_unit_sub[NUNITS]   = {0,1, 0,1,2,3,4,5, 0,1,2, 0,1, 0,1, 0, 0, 0};
__constant__ int c_chunk[8]           = {23328, 23328, 21632, 21632, 21632, 4096, 4096, 1000};

// batch-independent coefficient tensor (~1.39 MB)
__device__ float g_coef[COEF_TOT];

// idx buffers may be int32 (JAX x64 disabled downcasts the declared int64) or
// genuine int64. Detect via the raw 32-bit words: for little-endian int64
// values < 4096 the odd words are all zero; for an int32 sorted-unique index
// list word[1] = idx[1] >= 1. Reading 4096 bytes is in-bounds either way.
__device__ __forceinline__ int idx_is_i64(const int* w) {
    return (w[1] == 0) & (w[3] == 0) & (w[5] == 0);
}
__device__ __forceinline__ int idx_get(const int* w, int k, int is64) {
    return is64 ? w[2 * k] : w[k];
}

// ---------------------------------------------------------------------------
// Setup: build coefficients + seed output with bias
// ---------------------------------------------------------------------------
__global__ void build_coef_kernel(
    const float* __restrict__ m0, const float* __restrict__ m1,
    const float* __restrict__ m2, const float* __restrict__ m3,
    const float* __restrict__ m4,
    const float* __restrict__ W,  const float* __restrict__ mfc,
    const int* __restrict__ idx0, const int* __restrict__ idx1,
    const float* __restrict__ bias, float* __restrict__ out)
{
    int gid    = blockIdx.x * blockDim.x + threadIdx.x;
    int stride = gridDim.x * blockDim.x;

    if (gid < NB) out[gid] = bias[0];

    const float* masses[5] = {m0, m1, m2, m3, m4};
    float s = mfc[0];

    int is64_0 = idx_is_i64(idx0);
    int is64_1 = idx_is_i64(idx1);

    for (int e = gid; e < COEF_TOT; e += stride) {
        int l = 0;
        while (l < 7 && e >= c_coef_off[l + 1]) ++l;
        int local = e - c_coef_off[l];
        float v;
        if (l < 5) {
            int P = c_P[l];
            int ch = local / P;
            int px = local - ch * P;
            v = W[c_woff[l] + ch] * masses[l][px];
        } else if (l < 7) {
            // masked FC: binary-search the sorted unique index list
            const int* idx = (l == 5) ? idx0 : idx1;
            int is64 = (l == 5) ? is64_0 : is64_1;
            v = 0.0f;
            int lo = 0, hi = 1023;
            while (lo <= hi) {
                int mid = (lo + hi) >> 1;
                int t = idx_get(idx, mid, is64);
                if (t == local) { v = W[c_woff[l] + mid] * s; break; }
                if (t < local) lo = mid + 1; else hi = mid - 1;
            }
        } else {
            v = W[c_woff[7] + local] * s;
        }
        g_coef[e] = v;
    }
}

// ---------------------------------------------------------------------------
// Main: streaming weighted reduction. One block = one (batch, chunk) unit.
// ---------------------------------------------------------------------------
__global__ __launch_bounds__(256)
void reduce_kernel(
    const float* __restrict__ f0, const float* __restrict__ f1,
    const float* __restrict__ f2, const float* __restrict__ f3,
    const float* __restrict__ f4,
    const float* __restrict__ fc0, const float* __restrict__ fc1,
    const float* __restrict__ fc2,
    float* __restrict__ out)
{
    int unit  = blockIdx.x % NUNITS;
    int batch = blockIdx.x / NUNITS;

    int layer = c_unit_layer[unit];
    int sub   = c_unit_sub[unit];
    int elems = c_elems[layer];
    int chunk = c_chunk[layer];

    const float* bases[8] = {f0, f1, f2, f3, f4, fc0, fc1, fc2};

    const float4* __restrict__ d =
        reinterpret_cast<const float4*>(bases[layer] + (size_t)batch * elems + (size_t)sub * chunk);
    const float4* __restrict__ cf =
        reinterpret_cast<const float4*>(g_coef + c_coef_off[layer] + sub * chunk);

    int n4 = chunk >> 2;            // float4 count
    int n4_main = n4 & ~511;        // multiple of 2*256 for the unrolled body

    float acc0 = 0.0f, acc1 = 0.0f;

    for (int i = threadIdx.x; i < n4_main; i += 512) {
        float4 x0 = __ldg(d + i);
        float4 c0 = __ldg(cf + i);
        float4 x1 = __ldg(d + i + 256);
        float4 c1 = __ldg(cf + i + 256);
        acc0 = fmaf(x0.x, c0.x, acc0);
        acc0 = fmaf(x0.y, c0.y, acc0);
        acc0 = fmaf(x0.z, c0.z, acc0);
        acc0 = fmaf(x0.w, c0.w, acc0);
        acc1 = fmaf(x1.x, c1.x, acc1);
        acc1 = fmaf(x1.y, c1.y, acc1);
        acc1 = fmaf(x1.z, c1.z, acc1);
        acc1 = fmaf(x1.w, c1.w, acc1);
    }
    for (int i = n4_main + threadIdx.x; i < n4; i += 256) {
        float4 x = __ldg(d + i);
        float4 c = __ldg(cf + i);
        acc0 = fmaf(x.x, c.x, acc0);
        acc0 = fmaf(x.y, c.y, acc0);
        acc0 = fmaf(x.z, c.z, acc0);
        acc0 = fmaf(x.w, c.w, acc0);
    }

    float acc = acc0 + acc1;

    #pragma unroll
    for (int o = 16; o; o >>= 1)
        acc += __shfl_xor_sync(0xffffffffu, acc, o);

    __shared__ float sred[8];
    int w = threadIdx.x >> 5;
    if ((threadIdx.x & 31) == 0) sred[w] = acc;
    __syncthreads();

    if (threadIdx.x < 8) {
        float v = sred[threadIdx.x];
        #pragma unroll
        for (int o = 4; o; o >>= 1)
            v += __shfl_xor_sync(0xffu, v, o);
        if (threadIdx.x == 0)
            atomicAdd(&out[batch], v);
    }
}

// ---------------------------------------------------------------------------
// Launch: identify inputs by element count. Duplicate sizes are resolved by
// order of appearance (consistent in both plausible metadata orderings;
// mass0==mass1 and mass2==mass3==mass4 exactly, so mass order is moot).
// ---------------------------------------------------------------------------
extern "C" void kernel_launch(void* const* d_in, const int* in_sizes, int n_in,
                              void* d_out, int out_size)
{
    const float *fm[5] = {0,0,0,0,0};
    const float *ms[5] = {0,0,0,0,0};
    const float *fcp[3] = {0,0,0};
    const float *Wp = 0, *bp = 0, *mfcp = 0;
    const int *ix[2] = {0,0};

    int n729 = 0, n169 = 0, n22m = 0, nfc = 0, n1 = 0, nidx = 0;

    for (int i = 0; i < n_in; ++i) {
        int s = in_sizes[i];
        const void* p = d_in[i];
        switch (s) {
            case 23887872: fm[0] = (const float*)p; break;            // 512*64*27*27
            case 71663616: fm[1] = (const float*)p; break;            // 512*192*27*27
            case 33226752: fm[2] = (const float*)p; break;            // 512*384*13*13
            case 22151168: fm[3 + (n22m++)] = (const float*)p; break; // fmap3, fmap4
            case 2097152:  fcp[nfc++] = (const float*)p; break;       // fc0, fc1
            case 512000:   fcp[2] = (const float*)p; break;           // fc2
            case 729:      ms[n729++] = (const float*)p; break;       // mass0, mass1
            case 169:      ms[2 + (n169++)] = (const float*)p; break; // mass2..4
            case 1024:     ix[nidx++] = (const int*)p; break;         // idx0, idx1
            case 4200:     Wp = (const float*)p; break;
            case 1:
                if (n1 == 0) mfcp = (const float*)p; else bp = (const float*)p;
                ++n1;
                break;
            default: break;
        }
    }

    float* out = (float*)d_out;

    build_coef_kernel<<<512, 256>>>(ms[0], ms[1], ms[2], ms[3], ms[4],
                                    Wp, mfcp, ix[0], ix[1], bp, out);

    reduce_kernel<<<NB * NUNITS, 256>>>(fm[0], fm[1], fm[2], fm[3], fm[4],
                                        fcp[0], fcp[1], fcp[2], out);
}